// round 5
// baseline (speedup 1.0000x reference)
#include <cuda_runtime.h>

// Pruned RNNT loss — R5: ONE block per batch (768 thr). All 12 chunk operators
// (6x6 log-semiring, 16 composed 2-step iterations each) computed by 24 warps
// using width-8 shuffle subgroups (4 basis vectors per warp, 2 warps/chunk).
// Combine + apply happens intra-block after a syncthreads; only an 8-way
// partial mean crosses blocks. Single launch.

#define NEG    (-1.0e30f)
#define LOG2E  1.4426950408889634f
#define LN2f   0.6931471805599453f
#define LMAX   16
#define MAXB   8
#define MAXC   13
#define KCAP   200              // max composed k-steps (dataset: 192)
#define RROWS  (2*KCAP + 2)     // raw diagonal rows

__device__ float    g_partial[MAXB];
__device__ unsigned g_done = 0;

__device__ __forceinline__ float ex2f_(float x){float y;asm("ex2.approx.ftz.f32 %0,%1;":"=f"(y):"f"(x));return y;}
__device__ __forceinline__ float lg2f_(float x){float y;asm("lg2.approx.ftz.f32 %0,%1;":"=f"(y):"f"(x));return y;}

__global__ void __launch_bounds__(832) rnnt_kernel(
        const float* __restrict__ lp,   const int* __restrict__ tgt,
        const int*   __restrict__ tlen, const int* __restrict__ ulen,
        float* __restrict__ out, int T, int U, int V, int C, int B, int Kg) {
    __shared__ float sEr[RROWS][8], sBr[RROWS][8];     // raw band gains (row d-1)
    __shared__ float sG1[KCAP][8], sGm[KCAP][8], sG2[KCAP][8];
    __shared__ float s_ops[MAXC][6][8];                // [chunk][row][basis]
    __shared__ int   s_len[2];
    __shared__ float s_iv[2];

    const int b   = blockIdx.x;
    const int tid = threadIdx.x, lane = tid & 31, w = tid >> 5;
    const int Ut  = U - 1;
    const size_t sT = (size_t)U * V;
    const float* lpb  = lp + (size_t)b * T * sT;
    const int*   tgtb = tgt + b * Ut;

    // phase 0: lengths + init-vector scalars (overlap the gather below)
    if (tid == 0) s_len[0] = __ldg(tlen + b);
    if (tid == 1) s_len[1] = __ldg(ulen + b);
    if (tid == 2) s_iv[0]  = __ldg(lpb) * LOG2E;                    // gB(1,0)
    if (tid == 3) s_iv[1]  = __ldg(lpb + __ldg(tgtb)) * LOG2E;      // gE(0,1)

    // phase 1a: raw band gather, addresses depend only on T,U (no lengths)
    // row rr holds diagonal d = rr+1; slot s -> o = 2s-4-(d&1)
    const int ncell = (2 * Kg + 1) * 6;
    for (int idx = tid; idx < ncell; idx += blockDim.x) {
        int rr = idx / 6, s = idx - rr * 6;
        int d  = rr + 1;
        int o  = 2 * s - 4 - (d & 1);
        int t  = (d - o) >> 1, u = (d + o) >> 1;
        bool ob = (o >= -5) && (o <= 5);
        float ev = NEG, bv = NEG;
        if (ob && t >= 0 && t < T && u >= 1 && u <= Ut)
            ev = __ldg(lpb + (size_t)t * sT + (size_t)(u - 1) * V + __ldg(tgtb + (u - 1)));
        if (ob && t >= 1 && t <= T && u >= 0 && u <= Ut)
            bv = __ldg(lpb + (size_t)(t - 1) * sT + (size_t)u * V);
        sEr[rr][s] = ev; sBr[rr][s] = bv;
    }
    __syncthreads();

    const int tl = s_len[0], ul = s_len[1];
    const int dmax = tl + ul, p = dmax & 1, K = dmax >> 1;

    // phase 1b: compose 2-step operators (single parity, masks applied here)
    for (int idx = tid; idx < K * 6; idx += blockDim.x) {
        int k = idx / 6, s = idx - k * 6;
        int rrd = 2 * k + p + 1, rrm = rrd - 1;      // rows for diag d, d-1
        int u   = k + s - 1;                         // u of target cell
        bool mU  = (u <= ul), mUl = (u - 1 <= ul);
        float Ed = mU ? sEr[rrd][s] : NEG;
        float Bd = mU ? sBr[rrd][s] : NEG;
        int sL = s - p, sR = s + 1 - p;
        float El = (sL >= 0 && mUl) ? sEr[rrm][sL] : NEG;
        float Bl = (sL >= 0 && mUl) ? sBr[rrm][sL] : NEG;
        float Er = (sR <= 5 && mU)  ? sEr[rrm][sR] : NEG;
        float Br = (sR <= 5 && mU)  ? sBr[rrm][sR] : NEG;
        float G1 = (El + Ed) * LOG2E;                // from slot s-1
        float G2 = (Br + Bd) * LOG2E;                // from slot s+1
        float a  = (Bl + Ed) * LOG2E;
        float e  = (Er + Bd) * LOG2E;
        float m  = fmaxf(a, e);
        sG1[k][s] = G1; sG2[k][s] = G2;
        sGm[k][s] = m + lg2f_(ex2f_(a - m) + ex2f_(e - m));
    }
    __syncthreads();

    // phase 2: chunk c = w>>1; 4 basis recurrences per warp in width-8
    // subgroups. Lanes sl==0,7 are permanent-NEG sentinels (no boundary preds).
    {
        const int c   = w >> 1;
        const int seg = lane >> 3, sl = lane & 7;
        const bool act = (sl >= 1) && (sl <= 6);
        const int s    = act ? sl - 1 : 0;
        const int basis = (w & 1) * 4 + seg;         // 0..7 (>=6 unused)
        const int k0 = c * LMAX;
        const int nk = min(max(K - k0, 0), LMAX);
        float val = (act && (sl - 1) == basis) ? 0.0f : NEG;
        float p1 = (act && nk > 0) ? sG1[k0][s] : NEG;
        float pm = (act && nk > 0) ? sGm[k0][s] : NEG;
        float p2 = (act && nk > 0) ? sG2[k0][s] : NEG;
        for (int r = 0; r < nk; ++r) {
            bool hn = (r + 1 < nk);
            float n1 = (act && hn) ? sG1[k0 + r + 1][s] : NEG;
            float nm = (act && hn) ? sGm[k0 + r + 1][s] : NEG;
            float n2 = (act && hn) ? sG2[k0 + r + 1][s] : NEG;
            float dn = __shfl_up_sync  (0xffffffffu, val, 1, 8);  // v[slot-1]
            float up = __shfl_down_sync(0xffffffffu, val, 1, 8);  // v[slot+1]
            float x1 = dn + p1, x2 = val + pm, x3 = up + p2;
            float m  = fmaxf(fmaxf(x1, x2), x3);
            val = m + lg2f_(ex2f_(x1 - m) + ex2f_(x2 - m) + ex2f_(x3 - m));
            p1 = n1; pm = nm; p2 = n2;
        }
        if (act && basis < 6) s_ops[c][sl - 1][basis] = val;
    }
    __syncthreads();

    // phase 3: warp 0 applies the C operators serially, then global 8-way mean
    if (w == 0) {
        int s = min(lane, 5);
        float v;
        if (p == 0) v = (lane == 2) ? 0.0f : NEG;
        else        v = (lane == 2) ? s_iv[0] : ((lane == 3) ? s_iv[1] : NEG);

        const float* opp = &s_ops[0][s][0];
        float o0=opp[0],o1=opp[1],o2=opp[2],o3=opp[3],o4=opp[4],o5=opp[5];
        for (int cc = 0; cc < C; ++cc) {
            const float* npp = &s_ops[min(cc + 1, C - 1)][s][0];
            float q0=npp[0],q1=npp[1],q2=npp[2],q3=npp[3],q4=npp[4],q5=npp[5];
            float v0 = __shfl_sync(0xffffffffu, v, 0);
            float v1 = __shfl_sync(0xffffffffu, v, 1);
            float v2 = __shfl_sync(0xffffffffu, v, 2);
            float v3 = __shfl_sync(0xffffffffu, v, 3);
            float v4 = __shfl_sync(0xffffffffu, v, 4);
            float v5 = __shfl_sync(0xffffffffu, v, 5);
            float x0 = o0 + v0, x1 = o1 + v1, x2 = o2 + v2;
            float x3 = o3 + v3, x4 = o4 + v4, x5 = o5 + v5;
            float m = fmaxf(fmaxf(fmaxf(x0, x1), fmaxf(x2, x3)), fmaxf(x4, x5));
            float sm = ex2f_(x0 - m) + ex2f_(x1 - m) + ex2f_(x2 - m)
                     + ex2f_(x3 - m) + ex2f_(x4 - m) + ex2f_(x5 - m);
            v = m + lg2f_(sm);
            o0=q0;o1=q1;o2=q2;o3=q3;o4=q4;o5=q5;
        }
        const int slot_star = (ul - tl + 4 + p) >> 1;
        float r = __shfl_sync(0xffffffffu, -v * LN2f, slot_star);

        unsigned last = 0;
        if (lane == 0) {
            g_partial[b] = r;
            __threadfence();
            last = (atomicAdd(&g_done, 1u) == (unsigned)(B - 1)) ? 1u : 0u;
        }
        last = __shfl_sync(0xffffffffu, last, 0);
        if (last) {
            __threadfence();
            float sv = (lane < B) ? __ldcg(&g_partial[lane]) : 0.0f;
            #pragma unroll
            for (int wd = 16; wd; wd >>= 1) sv += __shfl_xor_sync(0xffffffffu, sv, wd);
            if (lane == 0) { out[0] = sv / (float)B; g_done = 0; }
        }
    }
}

extern "C" void kernel_launch(void* const* d_in, const int* in_sizes, int n_in,
                              void* d_out, int out_size) {
    const float* lp   = (const float*)d_in[0];   // [B,T,U,V] fp32
    const int*   tgt  = (const int*)  d_in[1];   // [B,U-1]
    const int*   tlen = (const int*)  d_in[2];   // [B]
    const int*   ulen = (const int*)  d_in[3];   // [B]

    const int B  = in_sizes[2];
    const int Ut = in_sizes[1] / B;
    const int U  = Ut + 1;
    const int V  = 512;
    const int T  = (int)(in_sizes[0] / ((long long)B * U * V));

    int Kg = (T + U - 1) >> 1;                   // max composed k-steps (192)
    if (Kg > KCAP) Kg = KCAP;
    int C = (Kg + LMAX - 1) / LMAX;              // chunks (dataset: 12)
    if (C > MAXC) C = MAXC;
    int threads = 64 * C;                        // 2 warps per chunk (768)

    rnnt_kernel<<<B, threads>>>(lp, tgt, tlen, ulen, (float*)d_out,
                                T, U, V, C, B, Kg);
}

// round 6
// speedup vs baseline: 1.1905x; 1.1905x over previous
#include <cuda_runtime.h>

// Pruned RNNT loss — R6: 96 blocks (12 chunks x 8 batches), 320 threads.
// Each block builds its chunk's 6x6 log-semiring operator by a PRODUCT TREE
// (16 tridiag step-ops -> 8 -> 4 -> 2 -> 1 dense), replacing the serial
// 16-step basis recurrence. Single global ticket; winner block stages all
// operators in smem and applies them per batch (8 warps), then the mean.
// All gathers are one-cell-per-thread, statically bounded (no dynamic loops
// around dependent loads — R5 lesson).

#define NEG    (-1.0e30f)
#define LOG2E  1.4426950408889634f
#define LN2f   0.6931471805599453f
#define LMAX   16
#define MAXB   8
#define MAXC   16
#define NROWS  (2*LMAX + 1)     // 33 raw diagonal rows per chunk window

__device__ float    g_ops[MAXB][MAXC][48];   // [b][chunk][row*8+col]
__device__ unsigned g_done = 0;

__device__ __forceinline__ float ex2f_(float x){float y;asm("ex2.approx.ftz.f32 %0,%1;":"=f"(y):"f"(x));return y;}
__device__ __forceinline__ float lg2f_(float x){float y;asm("lg2.approx.ftz.f32 %0,%1;":"=f"(y):"f"(x));return y;}

__device__ __forceinline__ float lse3_(float a, float b, float c) {
    float m = fmaxf(fmaxf(a, b), c);
    return m + lg2f_(ex2f_(a - m) + ex2f_(b - m) + ex2f_(c - m));
}
// dense 6x6 product entry: C[i][j] = LSE_k A[i][k] + B[k][j]  (row-major, pad 8)
__device__ __forceinline__ float lse6prod_(const float* A, const float* B, int i, int j) {
    float t0 = A[i*8+0] + B[0*8+j];
    float t1 = A[i*8+1] + B[1*8+j];
    float t2 = A[i*8+2] + B[2*8+j];
    float t3 = A[i*8+3] + B[3*8+j];
    float t4 = A[i*8+4] + B[4*8+j];
    float t5 = A[i*8+5] + B[5*8+j];
    float m = fmaxf(fmaxf(fmaxf(t0,t1),fmaxf(t2,t3)),fmaxf(t4,t5));
    float s = ex2f_(t0-m)+ex2f_(t1-m)+ex2f_(t2-m)
            + ex2f_(t3-m)+ex2f_(t4-m)+ex2f_(t5-m);
    return m + lg2f_(s);
}

__global__ void __launch_bounds__(320) rnnt_kernel(
        const float* __restrict__ lp,   const int* __restrict__ tgt,
        const int*   __restrict__ tlen, const int* __restrict__ ulen,
        float* __restrict__ out, int T, int U, int V, int C, int B) {
    __shared__ float sEr[NROWS][8], sBr[NROWS][8];
    __shared__ float sG1[LMAX][8], sGm[LMAX][8], sG2[LMAX][8];
    __shared__ float sL1[8][48], sL2[4][48], sL3[2][48], sL4[48];
    __shared__ float s_ops[MAXB][MAXC][48];
    __shared__ int   s_len[MAXB][2];
    __shared__ float s_iv[MAXB][2];
    __shared__ float s_red[MAXB];
    __shared__ int   s_last;

    const int chunk = blockIdx.x, b = blockIdx.y;
    const int tid = threadIdx.x, lane = tid & 31, w = tid >> 5;
    const int Ut  = U - 1;
    const int k0  = chunk * LMAX;
    const size_t sT = (size_t)U * V;
    const float* lpb  = lp + (size_t)b * T * sT;
    const int*   tgtb = tgt + b * Ut;

    // phase 0: lengths + init-vector scalars for ALL batches (overlaps gather)
    if (tid < B) {
        int bb = tid;
        const float* lpbb = lp + (size_t)bb * T * sT;
        s_len[bb][0] = __ldg(tlen + bb);
        s_len[bb][1] = __ldg(ulen + bb);
        int tg0 = __ldg(tgt + bb * Ut);
        s_iv[bb][0] = __ldg(lpbb) * LOG2E;               // gB(1,0)
        s_iv[bb][1] = __ldg(lpbb + tg0) * LOG2E;         // gE(0,1)
    }

    // phase 1a: raw band gather, ONE cell per thread, static bound
    if (tid < NROWS * 6) {
        int rr = tid / 6, s = tid - rr * 6;
        int d  = 2 * k0 + 1 + rr;
        int o  = 2 * s - 4 - (d & 1);
        int t  = (d - o) >> 1, u = (d + o) >> 1;
        bool ob = (o >= -5) && (o <= 5);
        float ev = NEG, bv = NEG;
        if (ob && t >= 0 && t < T && u >= 1 && u <= Ut)
            ev = __ldg(lpb + (size_t)t * sT + (size_t)(u - 1) * V + __ldg(tgtb + (u - 1)));
        if (ob && t >= 1 && t <= T && u >= 0 && u <= Ut)
            bv = __ldg(lpb + (size_t)(t - 1) * sT + (size_t)u * V);
        sEr[rr][s] = ev; sBr[rr][s] = bv;
    }
    __syncthreads();

    const int tl = s_len[b][0], ul = s_len[b][1];
    const int dmax = tl + ul, p = dmax & 1, K = dmax >> 1;

    // phase 1b: tridiagonal step operators (identity-pad beyond K)
    if (tid < LMAX * 6) {
        int k = tid / 6, s = tid - k * 6;
        float G1, Gm, G2;
        if (k0 + k < K) {
            int rrd = 2 * k + p + 1, rrm = rrd - 1;
            int u   = k0 + k + s - 1;
            bool mU  = (u <= ul), mUl = (u - 1 <= ul);
            float Ed = mU ? sEr[rrd][s] : NEG;
            float Bd = mU ? sBr[rrd][s] : NEG;
            int sL = s - p, sR = s + 1 - p;
            float El = (sL >= 0 && mUl) ? sEr[rrm][sL] : NEG;
            float Bl = (sL >= 0 && mUl) ? sBr[rrm][sL] : NEG;
            float Er = (sR <= 5 && mU)  ? sEr[rrm][sR] : NEG;
            float Br = (sR <= 5 && mU)  ? sBr[rrm][sR] : NEG;
            G1 = (El + Ed) * LOG2E;                      // from slot s-1
            G2 = (Br + Bd) * LOG2E;                      // from slot s+1
            float a = (Bl + Ed) * LOG2E;
            float e = (Er + Bd) * LOG2E;
            float m = fmaxf(a, e);
            Gm = m + lg2f_(ex2f_(a - m) + ex2f_(e - m));
        } else { G1 = NEG; Gm = 0.0f; G2 = NEG; }        // identity
        sG1[k][s] = G1; sGm[k][s] = Gm; sG2[k][s] = G2;
    }
    __syncthreads();

    // tree level 1: pairs of tridiag -> dense (pentadiagonal) [288 cells]
    if (tid < 8 * 36) {
        int m = tid / 36, rem = tid - m * 36;
        int i = rem / 6, j = rem - i * 6;
        const int A = 2 * m + 1, Bt = 2 * m;             // apply B first, A second
        // terms over k = j-1, j, j+1 :  triA(i,k) + triB(k,j)
        float t0 = NEG, t1, t2 = NEG;
        int k;
        k = j - 1;
        if (k >= 0) {
            float a = (k == i-1) ? sG1[A][i] : (k == i) ? sGm[A][i] : (k == i+1) ? sG2[A][i] : NEG;
            t0 = a + sG2[Bt][k];                         // B[k][j], j = k+1
        }
        k = j;
        {
            float a = (k == i-1) ? sG1[A][i] : (k == i) ? sGm[A][i] : (k == i+1) ? sG2[A][i] : NEG;
            t1 = a + sGm[Bt][k];                         // B[k][j], j = k
        }
        k = j + 1;
        if (k <= 5) {
            float a = (k == i-1) ? sG1[A][i] : (k == i) ? sGm[A][i] : (k == i+1) ? sG2[A][i] : NEG;
            t2 = a + sG1[Bt][k];                         // B[k][j], j = k-1
        }
        sL1[m][i*8 + j] = lse3_(t0, t1, t2);
    }
    __syncthreads();
    // level 2: 8 -> 4 [144 cells]
    if (tid < 4 * 36) {
        int m = tid / 36, rem = tid - m * 36;
        int i = rem / 6, j = rem - i * 6;
        sL2[m][i*8 + j] = lse6prod_(sL1[2*m + 1], sL1[2*m], i, j);
    }
    __syncthreads();
    // level 3: 4 -> 2 [72 cells]
    if (tid < 2 * 36) {
        int m = tid / 36, rem = tid - m * 36;
        int i = rem / 6, j = rem - i * 6;
        sL3[m][i*8 + j] = lse6prod_(sL2[2*m + 1], sL2[2*m], i, j);
    }
    __syncthreads();
    // level 4: 2 -> 1 [36 cells], write the chunk operator to global
    if (tid < 36) {
        int i = tid / 6, j = tid - i * 6;
        float v = lse6prod_(sL3[1], sL3[0], i, j);
        sL4[i*8 + j] = v;
        g_ops[b][chunk][i*8 + j] = v;
    }
    __threadfence();
    __syncthreads();
    if (tid == 0) {
        unsigned tk = atomicAdd(&g_done, 1u);
        s_last = (tk == (unsigned)(C * B - 1)) ? 1 : 0;
    }
    __syncthreads();
    if (!s_last) return;
    __threadfence();

    // winner: stage all operators into smem — compile-time-unrolled copy (MLP)
    {
        const float4* src = (const float4*)&g_ops[0][0][0];
        float4*       dst = (float4*)&s_ops[0][0][0];
        const int n4 = MAXB * MAXC * 48 / 4;             // 1536
        #pragma unroll
        for (int r = 0; r < (n4 + 319) / 320; ++r) {
            int i = tid + r * 320;
            if (i < n4) dst[i] = __ldcg(src + i);
        }
    }
    __syncthreads();

    // winner: 8 warps, warp w applies batch w's C operators serially
    if (w < B) {
        const int tlw = s_len[w][0], ulw = s_len[w][1];
        const int pw = (tlw + ulw) & 1;
        int s = min(lane, 5);
        float v;
        if (pw == 0) v = (lane == 2) ? 0.0f : NEG;
        else         v = (lane == 2) ? s_iv[w][0] : ((lane == 3) ? s_iv[w][1] : NEG);

        const float* opp = &s_ops[w][0][s*8];
        float o0=opp[0],o1=opp[1],o2=opp[2],o3=opp[3],o4=opp[4],o5=opp[5];
        for (int cc = 0; cc < C; ++cc) {
            const float* npp = &s_ops[w][min(cc + 1, C - 1)][s*8];
            float q0=npp[0],q1=npp[1],q2=npp[2],q3=npp[3],q4=npp[4],q5=npp[5];
            float v0 = __shfl_sync(0xffffffffu, v, 0);
            float v1 = __shfl_sync(0xffffffffu, v, 1);
            float v2 = __shfl_sync(0xffffffffu, v, 2);
            float v3 = __shfl_sync(0xffffffffu, v, 3);
            float v4 = __shfl_sync(0xffffffffu, v, 4);
            float v5 = __shfl_sync(0xffffffffu, v, 5);
            float x0 = o0 + v0, x1 = o1 + v1, x2 = o2 + v2;
            float x3 = o3 + v3, x4 = o4 + v4, x5 = o5 + v5;
            float m = fmaxf(fmaxf(fmaxf(x0, x1), fmaxf(x2, x3)), fmaxf(x4, x5));
            float sm = ex2f_(x0 - m) + ex2f_(x1 - m) + ex2f_(x2 - m)
                     + ex2f_(x3 - m) + ex2f_(x4 - m) + ex2f_(x5 - m);
            v = m + lg2f_(sm);
            o0=q0;o1=q1;o2=q2;o3=q3;o4=q4;o5=q5;
        }
        const int slot_star = (ulw - tlw + 4 + pw) >> 1;
        float r = __shfl_sync(0xffffffffu, -v * LN2f, slot_star);
        if (lane == 0) s_red[w] = r;
    }
    __syncthreads();
    if (w == 0) {
        float sv = (lane < B) ? s_red[lane] : 0.0f;
        #pragma unroll
        for (int wd = 16; wd; wd >>= 1) sv += __shfl_xor_sync(0xffffffffu, sv, wd);
        if (lane == 0) { out[0] = sv / (float)B; g_done = 0; }
    }
}

extern "C" void kernel_launch(void* const* d_in, const int* in_sizes, int n_in,
                              void* d_out, int out_size) {
    const float* lp   = (const float*)d_in[0];   // [B,T,U,V] fp32
    const int*   tgt  = (const int*)  d_in[1];   // [B,U-1]
    const int*   tlen = (const int*)  d_in[2];   // [B]
    const int*   ulen = (const int*)  d_in[3];   // [B]

    const int B  = in_sizes[2];
    const int Ut = in_sizes[1] / B;
    const int U  = Ut + 1;
    const int V  = 512;
    const int T  = (int)(in_sizes[0] / ((long long)B * U * V));

    const int Kg = (T + U - 1) >> 1;             // max composed k-steps (192)
    int C = (Kg + LMAX - 1) / LMAX;              // chunks (dataset: 12)
    if (C < 1) C = 1;
    if (C > MAXC) C = MAXC;

    dim3 grid(C, B);
    rnnt_kernel<<<grid, 320>>>(lp, tgt, tlen, ulen, (float*)d_out, T, U, V, C, B);
}